// round 12
// baseline (speedup 1.0000x reference)
#include <cuda_runtime.h>
#include <cstdint>

#define HD   19                 // hidden size
#define HJ   20                 // padded row stride
#define DD   64                 // input size
#define TPB  128
#define RPT  3                  // batch rows per thread
#define TROWS (TPB * RPT)       // 384 rows per tile
#define GRID 444                // 148 SMs x 3 resident CTAs (<= 152-SM GB300)

__device__ float g_partials[GRID];
__device__ unsigned long long g_bar = 0;   // monotonic epoch barrier counter

static __device__ __forceinline__ float tanha(float v) {
    float r; asm("tanh.approx.f32 %0,%1;" : "=f"(r) : "f"(v)); return r;
}
// forced-scalar shared load (prevents LDS.128 re-vectorization of broadcasts)
static __device__ __forceinline__ float lds32(uint32_t a) {
    float r; asm("ld.shared.f32 %0,[%1];" : "=f"(r) : "r"(a)); return r;
}
static __device__ __forceinline__ uint32_t saddr(const void* p) {
    uint32_t a;
    asm("{.reg .u64 t; cvta.to.shared.u64 t,%1; cvt.u32.u64 %0,t;}"
        : "=r"(a) : "l"(p));
    return a;
}

__global__ void __launch_bounds__(TPB, 3)
k_fused(const float* __restrict__ x,
        const float* __restrict__ Wi, const float* __restrict__ bi,
        const float* __restrict__ Wr, const float* __restrict__ Wo,
        const float* __restrict__ bo, const float* __restrict__ tau,
        const float* __restrict__ ta, const int* __restrict__ steps_p,
        float* __restrict__ out, float* __restrict__ hout, int B)
{
    __shared__ float sWi[DD * HJ];      // [k][j] = Wi[j][k]
    __shared__ float sWr[HD * HJ];
    __shared__ float sWo[HD * HJ];
    __shared__ float sBi[HJ], sBo[HJ], sBd[HJ];
    __shared__ float red[TPB];
    __shared__ float mst[TROWS * HD];   // mapped staging, reused for output staging

    const int tid = threadIdx.x;
    const int bid = blockIdx.x;

    // ---- phase A: |x| partial over grid-stride slice ----
    {
        const float4* x4 = (const float4*)x;
        const int n4 = (B * DD) / 4;
        float s = 0.f;
        for (int i = bid * TPB + tid; i < n4; i += GRID * TPB) {
            float4 v = x4[i];
            s += fabsf(v.x) + fabsf(v.y) + fabsf(v.z) + fabsf(v.w);
        }
#pragma unroll
        for (int o = 16; o > 0; o >>= 1) s += __shfl_down_sync(0xffffffffu, s, o);
        if ((tid & 31) == 0) red[tid >> 5] = s;
        __syncthreads();
        if (tid == 0) {
            float t = 0.f;
#pragma unroll
            for (int i = 0; i < TPB / 32; i++) t += red[i];
            g_partials[bid] = t;
        }
    }

    // ---- build weight tables while other CTAs finish phase A ----
    for (int i = tid; i < DD * HD; i += TPB) {
        int k = i / HD, j = i % HD;
        sWi[k * HJ + j] = Wi[j * DD + k];
    }
    for (int i = tid; i < HD * HD; i += TPB) {
        int k = i / HD, j = i % HD;
        sWr[k * HJ + j] = Wr[j * HD + k];
        sWo[k * HJ + j] = Wo[j * HD + k];
    }
    if (tid < HD) { sBi[tid] = bi[tid]; sBo[tid] = bo[tid]; }
    __syncthreads();            // g_partials[bid] written; red free

    // ---- grid barrier (monotonic, replay-safe) ----
    if (tid == 0) {
        __threadfence();
        unsigned long long my = atomicAdd(&g_bar, 1ULL) + 1ULL;
        unsigned long long tgt = ((my + GRID - 1) / GRID) * GRID;
        unsigned long long v;
        while (1) {
            asm volatile("ld.global.acquire.gpu.u64 %0,[%1];" : "=l"(v) : "l"(&g_bar));
            if (v >= tgt) break;
            __nanosleep(64);
        }
    }
    __syncthreads();

    // ---- urgency + bdt (identical fixed-order sum in every CTA) ----
    {
        float s = 0.f;
        for (int i = tid; i < GRID; i += TPB) s += g_partials[i];
        red[tid] = s;
        __syncthreads();
#pragma unroll
        for (int o = TPB / 2; o > 0; o >>= 1) {
            if (tid < o) red[tid] += red[tid + o];
            __syncthreads();
        }
        float urg = fmaxf(red[0] / (float)(B * DD), 0.01f);
        if (tid < HD) {
            float td = tau[tid] * (1.0f - ta[tid]) + ta[tid] / urg;
            td = fminf(fmaxf(td, 0.01f), 10.0f);
            sBd[tid] = 0.01f / td;
        }
        __syncthreads();
    }

    const int steps = *steps_p;
    const int ntiles = (B + TROWS - 1) / TROWS;
    const uint32_t aWi = saddr(sWi), aWr = saddr(sWr), aWo = saddr(sWo);
    const uint32_t aBd = saddr(sBd);

    for (int t = bid; t < ntiles; t += GRID) {
        const int base = t * TROWS;

        // ---- phase 1: mapped = x @ Wi^T + bi, staged to smem [j][r][tid] ----
        for (int r = 0; r < RPT; r++) {
            int row = base + r * TPB + tid;
            if (row < B) {
                const float4* xr = (const float4*)(x + (size_t)row * DD);
                float m[HD];
#pragma unroll
                for (int j = 0; j < HD; j++) m[j] = sBi[j];
#pragma unroll 4
                for (int q = 0; q < DD / 4; q++) {
                    float4 v = xr[q];
                    float vv[4] = {v.x, v.y, v.z, v.w};
#pragma unroll
                    for (int e = 0; e < 4; e++) {
                        uint32_t wb = aWi + (uint32_t)((q * 4 + e) * HJ) * 4u;
                        float xk = vv[e];
#pragma unroll
                        for (int j = 0; j < HD; j++)
                            m[j] = fmaf(xk, lds32(wb + 4u * j), m[j]);
                    }
                }
#pragma unroll
                for (int j = 0; j < HD; j++)
                    mst[(j * RPT + r) * TPB + tid] = m[j];
            }
        }
        // each thread reads only its own mst slots -> no sync needed here

        // ---- phase 2: recurrence, 3 rows/thread ----
        float h[RPT][HD];
#pragma unroll
        for (int r = 0; r < RPT; r++)
#pragma unroll
            for (int j = 0; j < HD; j++) h[r][j] = 0.f;

        for (int s = 0; s < steps; s++) {
            float a[RPT][HD];
#pragma unroll
            for (int j = 0; j < HD; j++) {
#pragma unroll
                for (int r = 0; r < RPT; r++)
                    a[r][j] = mst[(j * RPT + r) * TPB + tid];
            }
#pragma unroll
            for (int k = 0; k < HD; k++) {
                uint32_t wb = aWr + (uint32_t)(k * HJ) * 4u;
                float hk0 = h[0][k], hk1 = h[1][k], hk2 = h[2][k];
#pragma unroll
                for (int j = 0; j < HD; j++) {
                    float w = lds32(wb + 4u * j);
                    a[0][j] = fmaf(hk0, w, a[0][j]);
                    a[1][j] = fmaf(hk1, w, a[1][j]);
                    a[2][j] = fmaf(hk2, w, a[2][j]);
                }
            }
#pragma unroll
            for (int j = 0; j < HD; j++) {
                float b = lds32(aBd + 4u * j);
#pragma unroll
                for (int r = 0; r < RPT; r++)
                    h[r][j] = fmaf(b, tanha(a[r][j]) - h[r][j], h[r][j]);
            }
        }

        // ---- phase 3: out = h @ Wo^T + bo, stage + store ----
        __syncthreads();        // mst -> staging reuse crosses threads
        const int vrows = min(TROWS, B - base);
        const int vfl = vrows * HD;
#pragma unroll
        for (int r = 0; r < RPT; r++) {
            float o[HD];
#pragma unroll
            for (int j = 0; j < HD; j++) o[j] = sBo[j];
#pragma unroll
            for (int k = 0; k < HD; k++) {
                uint32_t wb = aWo + (uint32_t)(k * HJ) * 4u;
                float hk = h[r][k];
#pragma unroll
                for (int j = 0; j < HD; j++)
                    o[j] = fmaf(hk, lds32(wb + 4u * j), o[j]);
            }
#pragma unroll
            for (int j = 0; j < HD; j++)
                mst[(r * TPB + tid) * HD + j] = o[j];
        }
        __syncthreads();
        {
            float* go = out + (size_t)base * HD;
            for (int i = tid; i < vfl; i += TPB) go[i] = mst[i];
        }
        if (hout) {
            __syncthreads();
#pragma unroll
            for (int r = 0; r < RPT; r++)
#pragma unroll
                for (int j = 0; j < HD; j++)
                    mst[(r * TPB + tid) * HD + j] = h[r][j];
            __syncthreads();
            float* gh = hout + (size_t)base * HD;
            for (int i = tid; i < vfl; i += TPB) gh[i] = mst[i];
        }
        __syncthreads();        // before next tile overwrites mst
    }
}

extern "C" void kernel_launch(void* const* d_in, const int* in_sizes, int n_in,
                              void* d_out, int out_size) {
    const float* x   = (const float*)d_in[0];
    const float* Wi  = (const float*)d_in[1];
    const float* bi  = (const float*)d_in[2];
    const float* Wr  = (const float*)d_in[3];
    const float* Wo  = (const float*)d_in[4];
    const float* bo  = (const float*)d_in[5];
    const float* tau = (const float*)d_in[6];
    const float* ta  = (const float*)d_in[7];
    const int* steps = (const int*)d_in[8];

    const int nx = in_sizes[0];
    const int B  = nx / DD;

    float* out = (float*)d_out;
    long long bh = (long long)B * HD;
    float* hout = ((long long)out_size >= 2 * bh) ? (out + bh) : nullptr;

    k_fused<<<GRID, TPB>>>(x, Wi, bi, Wr, Wo, bo, tau, ta, steps, out, hout, B);
}